// round 7
// baseline (speedup 1.0000x reference)
#include <cuda_runtime.h>
#include <math.h>
#include <cstdint>

#define BATCH 64
#define SEQ   512
#define EDIM  256
#define HDIM2 256
#define G4H   1024
#define NTAGS 9
#define NTOK  (BATCH*SEQ)

typedef unsigned long long u64;

__device__ float g_xg[2u*NTOK*G4H];
__device__ float g_h [2u*NTOK*HDIM2];
__device__ float g_feats[NTOK*NTAGS];
__device__ float g_llh[BATCH];
__device__ int   g_flag[256 * 32];   // per-(dir,bg,ug) flags, one L2 line apart

__device__ __forceinline__ void fma2(u64& acc, u64 a, u64 b) {
    asm("fma.rn.f32x2 %0, %1, %2, %0;" : "+l"(acc) : "l"(a), "l"(b));
}
__device__ __forceinline__ u64 pack2(float x, float y) {
    u64 r; asm("mov.b64 %0, {%1, %2};" : "=l"(r) : "f"(x), "f"(y)); return r;
}
__device__ __forceinline__ float foldlohi(u64 v) {
    float lo, hi; asm("mov.b64 {%0, %1}, %2;" : "=f"(lo), "=f"(hi) : "l"(v)); return lo + hi;
}
__device__ __forceinline__ float2 unpk(u64 v) {
    float2 r; asm("mov.b64 {%0, %1}, %2;" : "=f"(r.x), "=f"(r.y) : "l"(v)); return r;
}
__device__ __forceinline__ float sigf(float x) { return __fdividef(1.f, 1.f + __expf(-x)); }
__device__ __forceinline__ float tanhfast(float x) {
    return 2.f * __fdividef(1.f, 1.f + __expf(-2.f * x)) - 1.f;
}
__device__ __forceinline__ int ld_acquire(const int* p) {
    int v; asm volatile("ld.acquire.gpu.b32 %0, [%1];" : "=r"(v) : "l"(p) : "memory");
    return v;
}
__device__ __forceinline__ void st_release(int* p, int v) {
    asm volatile("st.release.gpu.b32 [%0], %1;" :: "l"(p), "r"(v) : "memory");
}

// ============================================================================
// Kernel 1: fused embedding-gather + input projection SGEMM (f32x2)
//   M=32768, N=2048 (dir-major), K=256. BM=128, BN=128, BK=16, 256 thr, 8x8.
// ============================================================================
__global__ __launch_bounds__(256) void gemm_xg_kernel(
    const int* __restrict__ sent,
    const float* __restrict__ emb,
    const float* __restrict__ wihf, const float* __restrict__ wihb,
    const float* __restrict__ bihf, const float* __restrict__ bhhf,
    const float* __restrict__ bihb, const float* __restrict__ bhhb)
{
    __shared__ float As[16 * 132];
    __shared__ float Bs[16 * 128];

    const int tid = threadIdx.x;
    if (blockIdx.x == 0 && blockIdx.y == 0) g_flag[tid * 32] = 0;  // reset lstm flags

    const int ntile = blockIdx.x;
    const int mtile = blockIdx.y;
    const int dir   = ntile >> 3;
    const float* __restrict__ W = dir ? wihb : wihf;

    const int rowA = tid >> 2;
    const int f4k  = tid & 3;
    const int idx0 = sent[mtile * 128 + rowA];
    const int idx1 = sent[mtile * 128 + rowA + 64];
    const int nlb0 = (ntile * 128 + rowA) & 1023;
    const int nlb1 = (ntile * 128 + rowA + 64) & 1023;

    float4 av0 = *reinterpret_cast<const float4*>(emb + (size_t)idx0 * EDIM + f4k * 4);
    float4 av1 = *reinterpret_cast<const float4*>(emb + (size_t)idx1 * EDIM + f4k * 4);
    float4 bv0 = *reinterpret_cast<const float4*>(W + (size_t)nlb0 * EDIM + f4k * 4);
    float4 bv1 = *reinterpret_cast<const float4*>(W + (size_t)nlb1 * EDIM + f4k * 4);

    u64 acc[4][8];
#pragma unroll
    for (int i = 0; i < 4; i++)
#pragma unroll
        for (int j = 0; j < 8; j++) acc[i][j] = 0ull;

    const int ty = tid >> 4, tx = tid & 15;

    for (int kb = 0; kb < EDIM; kb += 16) {
        As[(f4k * 4 + 0) * 132 + rowA] = av0.x;
        As[(f4k * 4 + 1) * 132 + rowA] = av0.y;
        As[(f4k * 4 + 2) * 132 + rowA] = av0.z;
        As[(f4k * 4 + 3) * 132 + rowA] = av0.w;
        As[(f4k * 4 + 0) * 132 + rowA + 64] = av1.x;
        As[(f4k * 4 + 1) * 132 + rowA + 64] = av1.y;
        As[(f4k * 4 + 2) * 132 + rowA + 64] = av1.z;
        As[(f4k * 4 + 3) * 132 + rowA + 64] = av1.w;
        Bs[(f4k * 4 + 0) * 128 + rowA] = bv0.x;
        Bs[(f4k * 4 + 1) * 128 + rowA] = bv0.y;
        Bs[(f4k * 4 + 2) * 128 + rowA] = bv0.z;
        Bs[(f4k * 4 + 3) * 128 + rowA] = bv0.w;
        Bs[(f4k * 4 + 0) * 128 + rowA + 64] = bv1.x;
        Bs[(f4k * 4 + 1) * 128 + rowA + 64] = bv1.y;
        Bs[(f4k * 4 + 2) * 128 + rowA + 64] = bv1.z;
        Bs[(f4k * 4 + 3) * 128 + rowA + 64] = bv1.w;
        __syncthreads();

        if (kb + 16 < EDIM) {
            av0 = *reinterpret_cast<const float4*>(emb + (size_t)idx0 * EDIM + kb + 16 + f4k * 4);
            av1 = *reinterpret_cast<const float4*>(emb + (size_t)idx1 * EDIM + kb + 16 + f4k * 4);
            bv0 = *reinterpret_cast<const float4*>(W + (size_t)nlb0 * EDIM + kb + 16 + f4k * 4);
            bv1 = *reinterpret_cast<const float4*>(W + (size_t)nlb1 * EDIM + kb + 16 + f4k * 4);
        }

#pragma unroll
        for (int k = 0; k < 16; k++) {
            const float* ap = As + k * 132 + ty * 8;
            ulonglong2 A01 = *reinterpret_cast<const ulonglong2*>(ap);
            ulonglong2 A23 = *reinterpret_cast<const ulonglong2*>(ap + 4);
            const float* bp = Bs + k * 128 + tx * 8;
            float4 b0 = *reinterpret_cast<const float4*>(bp);
            float4 b1 = *reinterpret_cast<const float4*>(bp + 4);
            u64 am[4] = {A01.x, A01.y, A23.x, A23.y};
            u64 bn[8];
            bn[0] = pack2(b0.x, b0.x); bn[1] = pack2(b0.y, b0.y);
            bn[2] = pack2(b0.z, b0.z); bn[3] = pack2(b0.w, b0.w);
            bn[4] = pack2(b1.x, b1.x); bn[5] = pack2(b1.y, b1.y);
            bn[6] = pack2(b1.z, b1.z); bn[7] = pack2(b1.w, b1.w);
#pragma unroll
            for (int i = 0; i < 4; i++)
#pragma unroll
                for (int j = 0; j < 8; j++) fma2(acc[i][j], am[i], bn[j]);
        }
        __syncthreads();
    }

    const int n0  = ntile * 128 + tx * 8;
    const int nl0 = n0 & 1023;
    const float* __restrict__ bih = dir ? bihb : bihf;
    const float* __restrict__ bhh = dir ? bhhb : bhhf;
    float bias[8];
#pragma unroll
    for (int j = 0; j < 8; j++) bias[j] = bih[nl0 + j] + bhh[nl0 + j];

#pragma unroll
    for (int i2 = 0; i2 < 4; i2++) {
        float2 v[8];
#pragma unroll
        for (int j = 0; j < 8; j++) v[j] = unpk(acc[i2][j]);
        const int m0 = mtile * 128 + ty * 8 + 2 * i2;
        float4 oa0, oa1, ob0, ob1;
        oa0.x = v[0].x + bias[0]; oa0.y = v[1].x + bias[1]; oa0.z = v[2].x + bias[2]; oa0.w = v[3].x + bias[3];
        oa1.x = v[4].x + bias[4]; oa1.y = v[5].x + bias[5]; oa1.z = v[6].x + bias[6]; oa1.w = v[7].x + bias[7];
        ob0.x = v[0].y + bias[0]; ob0.y = v[1].y + bias[1]; ob0.z = v[2].y + bias[2]; ob0.w = v[3].y + bias[3];
        ob1.x = v[4].y + bias[4]; ob1.y = v[5].y + bias[5]; ob1.z = v[6].y + bias[6]; ob1.w = v[7].y + bias[7];
        float* p0 = g_xg + ((size_t)dir * NTOK + m0) * G4H + nl0;
        float* p1 = g_xg + ((size_t)dir * NTOK + m0 + 1) * G4H + nl0;
        *reinterpret_cast<float4*>(p0)     = oa0;
        *reinterpret_cast<float4*>(p0 + 4) = oa1;
        *reinterpret_cast<float4*>(p1)     = ob0;
        *reinterpret_cast<float4*>(p1 + 4) = ob1;
    }
}

// ============================================================================
// Kernel 2: persistent BiLSTM. 256 CTAs = dir(2) x bg(8) x ug(16), 2/SM.
//   Handshake: producer tid0 st.release.gpu -> per-CTA flag (own L2 line);
//   consumers tid<16 acquire-poll the 16 group flags in parallel, one BAR.
//   Matvec reads h(t-1) directly from L2 via __ldca (no SMEM staging):
//   each address is read exactly once after a single write (no staleness);
//   the 8 kc lanes cover one contiguous 128B line per (q,b) -> coalesced.
//   Thread (r2 0..31, kc 0..7): rows {r2, r2+32}, 8 batches, 32 k.
// ============================================================================
#define PRE_LD 67

__global__ __launch_bounds__(256, 2) void lstm_kernel(
    const float* __restrict__ whhf, const float* __restrict__ whhb)
{
    __shared__ float pre[64 * PRE_LD];   // [row][kc*8 + b]

    const int tid = threadIdx.x;
    const int blk = blockIdx.x;
    const int dir = blk >> 7;
    const int bg  = (blk >> 4) & 7;
    const int ug  = blk & 15;
    const float* __restrict__ whh = dir ? whhb : whhf;

    const int kc = tid & 7;           // k slice
    const int r2 = tid >> 3;          // 0..31 -> rows r2, r2+32

    // register weights: rows A=r2 (gate r2>>4), B=r2+32 (gate +2)
    u64 wA[16], wB[16];
    {
        const int GA = r2 >> 4, uu = r2 & 15;
        const int growA = GA * 256 + ug * 16 + uu;
        const int growB = (GA + 2) * 256 + ug * 16 + uu;
#pragma unroll
        for (int q = 0; q < 8; q++) {
            ulonglong2 a = *reinterpret_cast<const ulonglong2*>(whh + (size_t)growA * HDIM2 + q * 32 + kc * 4);
            ulonglong2 b = *reinterpret_cast<const ulonglong2*>(whh + (size_t)growB * HDIM2 + q * 32 + kc * 4);
            wA[2 * q] = a.x; wA[2 * q + 1] = a.y;
            wB[2 * q] = b.x; wB[2 * q + 1] = b.y;
        }
    }

    const int gb = (tid >> 4) & 7;    // gate phase: batch 0..7 (tid<128)
    const int gu = tid & 15;          // unit-in-slice
    const int b_glob = bg * 8 + gb;
    const int unit = ug * 16 + gu;
    const int grp = dir * 8 + bg;
    int* myflag = g_flag + (grp * 16 + ug) * 32;
    const int* pollflag = g_flag + (grp * 16 + (tid & 15)) * 32;
    float c_state = 0.f;

    for (int t = 0; t < SEQ; t++) {
        const int pos = dir ? (SEQ - 1 - t) : t;

        // prefetch x-preacts before the inter-CTA wait (gate threads only)
        float x0 = 0.f, x1 = 0.f, x2 = 0.f, x3 = 0.f;
        if (tid < 128) {
            const float* xp = g_xg + ((size_t)dir * NTOK + (size_t)b_glob * SEQ + pos) * G4H + unit;
            x0 = __ldcs(xp);
            x1 = __ldcs(xp + 256);
            x2 = __ldcs(xp + 512);
            x3 = __ldcs(xp + 768);
        }

        if (t > 0) {
            // parallel acquire-poll: 16 threads, 16 flags, 16 distinct L2 lines
            if (tid < 16) {
                while (ld_acquire(pollflag) < t) { }
            }
            __syncthreads();

            const int ppos = dir ? (pos + 1) : (pos - 1);
            const float* hb = g_h + ((size_t)(dir * BATCH + bg * 8) * SEQ + ppos) * HDIM2 + kc * 4;

            // matvec: 2 rows x 8 batches x 32 k per thread; h via L1-cached LDG
            u64 aA[8], aB[8];
#pragma unroll
            for (int b = 0; b < 8; b++) { aA[b] = 0ull; aB[b] = 0ull; }
#pragma unroll
            for (int q = 0; q < 8; q++) {
#pragma unroll
                for (int b = 0; b < 8; b++) {
                    const longlong2 hl = __ldca(reinterpret_cast<const longlong2*>(
                        hb + (size_t)b * (SEQ * HDIM2) + q * 32));
                    const u64 hx = (u64)hl.x, hy = (u64)hl.y;
                    fma2(aA[b], wA[2 * q],     hx);
                    fma2(aA[b], wA[2 * q + 1], hy);
                    fma2(aB[b], wB[2 * q],     hx);
                    fma2(aB[b], wB[2 * q + 1], hy);
                }
            }
#pragma unroll
            for (int b = 0; b < 8; b++) {
                pre[r2 * PRE_LD + kc * 8 + b]        = foldlohi(aA[b]);
                pre[(r2 + 32) * PRE_LD + kc * 8 + b] = foldlohi(aB[b]);
            }
            __syncthreads();
        }

        // gate phase (128 threads): thread owns (batch gb, unit gu)
        if (tid < 128) {
            float pi = x0, pf = x1, pg = x2, po = x3;
            if (t > 0) {
#pragma unroll
                for (int k8 = 0; k8 < 8; k8++) {
                    pi += pre[(0 * 16 + gu) * PRE_LD + k8 * 8 + gb];
                    pf += pre[(1 * 16 + gu) * PRE_LD + k8 * 8 + gb];
                    pg += pre[(2 * 16 + gu) * PRE_LD + k8 * 8 + gb];
                    po += pre[(3 * 16 + gu) * PRE_LD + k8 * 8 + gb];
                }
            }
            c_state = sigf(pf) * c_state + sigf(pi) * tanhfast(pg);
            const float hv = sigf(po) * tanhfast(c_state);
            __stcg(&g_h[((size_t)(dir * BATCH + b_glob) * SEQ + pos) * HDIM2 + unit], hv);
        }

        __syncthreads();            // orders all gate-thread h stores before release
        if (tid == 0) st_release(myflag, t + 1);
    }
}

// ============================================================================
// Kernel 3: output projection
// ============================================================================
__global__ __launch_bounds__(256) void feats_kernel(
    const float* __restrict__ wout, const float* __restrict__ bout)
{
    __shared__ float wsm[NTAGS * 512];
    const int tid = threadIdx.x;
    for (int i = tid; i < NTAGS * 512; i += 256) wsm[i] = wout[i];
    __syncthreads();

    const int lane = tid & 31;
    const int warp = tid >> 5;

#pragma unroll
    for (int pass = 0; pass < 4; pass++) {
        const int m = blockIdx.x * 32 + pass * 8 + warp;
        const float* h0 = g_h + (size_t)m * HDIM2;
        const float* h1 = g_h + (size_t)NTOK * HDIM2 + (size_t)m * HDIM2;
        float acc[NTAGS];
#pragma unroll
        for (int tg = 0; tg < NTAGS; tg++) acc[tg] = 0.f;

#pragma unroll
        for (int kk = 0; kk < 16; kk++) {
            const int k = kk * 32 + lane;
            const float hv = (k < 256) ? h0[k] : h1[k - 256];
#pragma unroll
            for (int tg = 0; tg < NTAGS; tg++) acc[tg] += hv * wsm[tg * 512 + k];
        }
#pragma unroll
        for (int tg = 0; tg < NTAGS; tg++)
            for (int off = 16; off; off >>= 1)
                acc[tg] += __shfl_down_sync(0xffffffffu, acc[tg], off);
        if (lane == 0) {
#pragma unroll
            for (int tg = 0; tg < NTAGS; tg++)
                g_feats[(size_t)m * NTAGS + tg] = acc[tg] + bout[tg];
        }
    }
}

// ============================================================================
// Kernel 4: CRF per-sequence llh (mask all-ones)
// ============================================================================
__global__ __launch_bounds__(32) void crf_kernel(
    const int* __restrict__ tags,
    const float* __restrict__ startt, const float* __restrict__ endt,
    const float* __restrict__ trans)
{
    const int b = blockIdx.x;
    const int lane = threadIdx.x;
    const float* __restrict__ em = g_feats + (size_t)b * SEQ * NTAGS;
    const int* __restrict__ tg = tags + (size_t)b * SEQ;

    float sc = 0.f;
    for (int s = lane; s < SEQ; s += 32) {
        const int tc = tg[s];
        sc += em[s * NTAGS + tc];
        if (s > 0) sc += trans[tg[s - 1] * NTAGS + tc];
    }
    for (int off = 16; off; off >>= 1) sc += __shfl_down_sync(0xffffffffu, sc, off);

    const int j = lane < NTAGS ? lane : NTAGS - 1;
    float tcol[NTAGS];
#pragma unroll
    for (int i = 0; i < NTAGS; i++) tcol[i] = trans[i * NTAGS + j];

    float alpha = startt[j] + em[j];
    for (int s = 1; s < SEQ; s++) {
        float v[NTAGS];
        float mx = -1e30f;
#pragma unroll
        for (int i = 0; i < NTAGS; i++) {
            const float ai = __shfl_sync(0xffffffffu, alpha, i);
            v[i] = ai + tcol[i];
            mx = fmaxf(mx, v[i]);
        }
        float sum = 0.f;
#pragma unroll
        for (int i = 0; i < NTAGS; i++) sum += __expf(v[i] - mx);
        alpha = mx + __logf(sum) + em[s * NTAGS + j];
    }

    float z = (lane < NTAGS) ? (alpha + endt[j]) : -1e30f;
    float mz = z;
    for (int off = 16; off; off >>= 1) mz = fmaxf(mz, __shfl_down_sync(0xffffffffu, mz, off));
    mz = __shfl_sync(0xffffffffu, mz, 0);
    float ez = __expf(z - mz);
    for (int off = 16; off; off >>= 1) ez += __shfl_down_sync(0xffffffffu, ez, off);

    if (lane == 0) {
        const float logZ = mz + __logf(ez);
        const float score = sc + startt[tg[0]] + endt[tg[SEQ - 1]];
        g_llh[b] = score - logZ;
    }
}

__global__ void final_kernel(float* out) {
    __shared__ float red[64];
    const int t = threadIdx.x;
    red[t] = g_llh[t];
    __syncthreads();
    for (int off = 32; off; off >>= 1) {
        if (t < off) red[t] += red[t + off];
        __syncthreads();
    }
    if (t == 0) out[0] = -red[0] / (float)BATCH;
}

// ============================================================================
extern "C" void kernel_launch(void* const* d_in, const int* in_sizes, int n_in,
                              void* d_out, int out_size)
{
    const int*   sent  = (const int*)  d_in[0];
    const int*   tags  = (const int*)  d_in[1];
    const float* emb   = (const float*)d_in[3];
    const float* wihf  = (const float*)d_in[4];
    const float* whhf  = (const float*)d_in[5];
    const float* bihf  = (const float*)d_in[6];
    const float* bhhf  = (const float*)d_in[7];
    const float* wihb  = (const float*)d_in[8];
    const float* whhb  = (const float*)d_in[9];
    const float* bihb  = (const float*)d_in[10];
    const float* bhhb  = (const float*)d_in[11];
    const float* wout  = (const float*)d_in[12];
    const float* bout  = (const float*)d_in[13];
    const float* startt= (const float*)d_in[14];
    const float* endt  = (const float*)d_in[15];
    const float* trans = (const float*)d_in[16];

    gemm_xg_kernel<<<dim3(16, 256), 256>>>(sent, emb, wihf, wihb, bihf, bhhf, bihb, bhhb);
    lstm_kernel<<<256, 256>>>(whhf, whhb);
    feats_kernel<<<1024, 256>>>(wout, bout);
    crf_kernel<<<64, 32>>>(tags, startt, endt, trans);
    final_kernel<<<1, 64>>>((float*)d_out);
}

// round 8
// speedup vs baseline: 1.1510x; 1.1510x over previous
#include <cuda_runtime.h>
#include <math.h>
#include <cstdint>

#define BATCH 64
#define SEQ   512
#define EDIM  256
#define HDIM2 256
#define NTAGS 9
#define NTOK  (BATCH*SEQ)

typedef unsigned long long u64;

__device__ float g_h[2u*NTOK*HDIM2];
__device__ float g_feats[NTOK*NTAGS];
__device__ float g_llh[BATCH];
__device__ int   g_cnt[8];

__device__ __forceinline__ void fma2(u64& acc, u64 a, u64 b) {
    asm("fma.rn.f32x2 %0, %1, %2, %0;" : "+l"(acc) : "l"(a), "l"(b));
}
__device__ __forceinline__ float foldlohi(u64 v) {
    float lo, hi; asm("mov.b64 {%0, %1}, %2;" : "=f"(lo), "=f"(hi) : "l"(v)); return lo + hi;
}
__device__ __forceinline__ float sigf(float x) { return __fdividef(1.f, 1.f + __expf(-x)); }
__device__ __forceinline__ float tanhfast(float x) {
    return 2.f * __fdividef(1.f, 1.f + __expf(-2.f * x)) - 1.f;
}

__global__ void init_kernel() {
    if (threadIdx.x < 8) g_cnt[threadIdx.x] = 0;
}

// ============================================================================
// Fused persistent BiLSTM: gate = W_ih·x_t + W_hh·h_{t-1} + bias, computed
// per step inside the recurrence. 128 CTAs = dir(2) x bg(4) x ug(16),
// 16 batches/CTA, 1 CTA/SM.
//   Thread (r2 0..31, kc 0..7): rows {r2, r2+32}, 16 batches, k-slice of 64
//   per 256-k half. Weights fully register-resident (64 u64). x/h in SMEM:
//   warp lanes (8 kc x 16B) read one contiguous 128B line -> 1 wavefront.
//   x-half matvec runs BEFORE the inter-CTA wait (fills handshake latency);
//   x_{t+1} emb rows staged during the wait. Handshake = R2-proven counter.
// ============================================================================
#define HLD   260
#define PRELD 136   // row stride = 8*17

__global__ __launch_bounds__(256, 1) void bilstm_kernel(
    const float* __restrict__ wihf, const float* __restrict__ whhf,
    const float* __restrict__ bihf, const float* __restrict__ bhhf,
    const float* __restrict__ wihb, const float* __restrict__ whhb,
    const float* __restrict__ bihb, const float* __restrict__ bhhb,
    const int* __restrict__ sent, const float* __restrict__ emb)
{
    extern __shared__ float sm[];
    float* xb0  = sm;                    // x double buffer [2][16*HLD]
    float* hb   = sm + 2 * 16 * HLD;     // h buffer [16*HLD]
    float* preX = sm + 3 * 16 * HLD;     // [64][PRELD]
    float* preH = preX + 64 * PRELD;     // [64][PRELD]

    const int tid = threadIdx.x;
    const int blk = blockIdx.x;
    const int dir = blk >> 6;
    const int bg  = (blk >> 4) & 3;
    const int ug  = blk & 15;

    const float* __restrict__ wih = dir ? wihb : wihf;
    const float* __restrict__ whh = dir ? whhb : whhf;

    const int kc = tid & 7;       // k slice within each 256-k half
    const int r2 = tid >> 3;      // 0..31 -> rows r2 (gates 0/1), r2+32 (gates 2/3)
    const int GA = r2 >> 4;
    const int growA = GA * 256 + ug * 16 + (r2 & 15);
    const int growB = growA + 512;

    // register weights: wx (input proj), wh (recurrent); [row][c][pair]
    u64 wx[32], wh[32];
#pragma unroll
    for (int row = 0; row < 2; row++) {
        const int grow = row ? growB : growA;
#pragma unroll
        for (int c = 0; c < 8; c++) {
            const int k0 = c * 32 + kc * 4;
            ulonglong2 a = *reinterpret_cast<const ulonglong2*>(wih + (size_t)grow * EDIM + k0);
            wx[(row * 8 + c) * 2]     = a.x;
            wx[(row * 8 + c) * 2 + 1] = a.y;
            ulonglong2 b = *reinterpret_cast<const ulonglong2*>(whh + (size_t)grow * HDIM2 + k0);
            wh[(row * 8 + c) * 2]     = b.x;
            wh[(row * 8 + c) * 2 + 1] = b.y;
        }
    }

    // gate-phase mapping + biases
    const int gb = tid >> 4;      // batch 0..15
    const int gu = tid & 15;      // unit-in-slice
    const int b_glob = bg * 16 + gb;
    const int unit = ug * 16 + gu;
    const float* __restrict__ bihp = dir ? bihb : bihf;
    const float* __restrict__ bhhp = dir ? bhhb : bhhf;
    const float bias0 = bihp[0 * 256 + unit] + bhhp[0 * 256 + unit];
    const float bias1 = bihp[1 * 256 + unit] + bhhp[1 * 256 + unit];
    const float bias2 = bihp[2 * 256 + unit] + bhhp[2 * 256 + unit];
    const float bias3 = bihp[3 * 256 + unit] + bhhp[3 * 256 + unit];

    // stage x for t=0 into buffer 0
    {
        const int pos0 = dir ? (SEQ - 1) : 0;
#pragma unroll
        for (int p = 0; p < 4; p++) {
            const int id = tid + p * 256;
            const int b = id >> 6, kf4 = id & 63;
            const int erow = sent[(bg * 16 + b) * SEQ + pos0];
            float4 v = *reinterpret_cast<const float4*>(emb + (size_t)erow * EDIM + kf4 * 4);
            *reinterpret_cast<float4*>(xb0 + b * HLD + kf4 * 4) = v;
        }
    }
    __syncthreads();

    const int cnt_idx = dir * 4 + bg;
    float c_state = 0.f;

    for (int t = 0; t < SEQ; t++) {
        const int pos = dir ? (SEQ - 1 - t) : t;
        const float* xb = xb0 + (t & 1) * (16 * HLD);

        // ---- Phase A: x-half matvec (independent of h) -> preX ----
#pragma unroll
        for (int bg2 = 0; bg2 < 2; bg2++) {
            u64 acc[16];
#pragma unroll
            for (int i = 0; i < 16; i++) acc[i] = 0ull;
#pragma unroll
            for (int c = 0; c < 8; c++) {
#pragma unroll
                for (int b = 0; b < 8; b++) {
                    const ulonglong2 hv = *reinterpret_cast<const ulonglong2*>(
                        xb + (bg2 * 8 + b) * HLD + c * 32 + kc * 4);
                    fma2(acc[b],     wx[(0 * 8 + c) * 2],     hv.x);
                    fma2(acc[b],     wx[(0 * 8 + c) * 2 + 1], hv.y);
                    fma2(acc[8 + b], wx[(1 * 8 + c) * 2],     hv.x);
                    fma2(acc[8 + b], wx[(1 * 8 + c) * 2 + 1], hv.y);
                }
            }
#pragma unroll
            for (int b = 0; b < 8; b++) {
                preX[r2 * PRELD + kc * 17 + bg2 * 8 + b]        = foldlohi(acc[b]);
                preX[(r2 + 32) * PRELD + kc * 17 + bg2 * 8 + b] = foldlohi(acc[8 + b]);
            }
        }

        // ---- stage x for t+1 (LDGs overlap the wait below) ----
        if (t + 1 < SEQ) {
            const int npos = dir ? (SEQ - 2 - t) : (t + 1);
            float* xn = xb0 + ((t + 1) & 1) * (16 * HLD);
#pragma unroll
            for (int p = 0; p < 4; p++) {
                const int id = tid + p * 256;
                const int b = id >> 6, kf4 = id & 63;
                const int erow = sent[(bg * 16 + b) * SEQ + npos];
                float4 v = *reinterpret_cast<const float4*>(emb + (size_t)erow * EDIM + kf4 * 4);
                *reinterpret_cast<float4*>(xn + b * HLD + kf4 * 4) = v;
            }
        }

        if (t > 0) {
            // ---- wait for h(t-1) from all 16 CTAs of this (dir,bg) group ----
            if (tid == 0) {
                volatile int* c = &g_cnt[cnt_idx];
                const int target = 16 * t;
                while (*c < target) { }
            }
            __syncthreads();
            const int ppos = dir ? (pos + 1) : (pos - 1);
#pragma unroll
            for (int p = 0; p < 4; p++) {
                const int id = tid + p * 256;
                const int b = id >> 6, kf4 = id & 63;
                float4 v = __ldcg(reinterpret_cast<const float4*>(
                    g_h + ((size_t)(dir * BATCH + bg * 16 + b) * SEQ + ppos) * HDIM2 + kf4 * 4));
                *reinterpret_cast<float4*>(hb + b * HLD + kf4 * 4) = v;
            }
            __syncthreads();

            // ---- Phase C: h-half matvec -> preH ----
#pragma unroll
            for (int bg2 = 0; bg2 < 2; bg2++) {
                u64 acc[16];
#pragma unroll
                for (int i = 0; i < 16; i++) acc[i] = 0ull;
#pragma unroll
                for (int c = 0; c < 8; c++) {
#pragma unroll
                    for (int b = 0; b < 8; b++) {
                        const ulonglong2 hv = *reinterpret_cast<const ulonglong2*>(
                            hb + (bg2 * 8 + b) * HLD + c * 32 + kc * 4);
                        fma2(acc[b],     wh[(0 * 8 + c) * 2],     hv.x);
                        fma2(acc[b],     wh[(0 * 8 + c) * 2 + 1], hv.y);
                        fma2(acc[8 + b], wh[(1 * 8 + c) * 2],     hv.x);
                        fma2(acc[8 + b], wh[(1 * 8 + c) * 2 + 1], hv.y);
                    }
                }
#pragma unroll
                for (int b = 0; b < 8; b++) {
                    preH[r2 * PRELD + kc * 17 + bg2 * 8 + b]        = foldlohi(acc[b]);
                    preH[(r2 + 32) * PRELD + kc * 17 + bg2 * 8 + b] = foldlohi(acc[8 + b]);
                }
            }
        }
        __syncthreads();

        // ---- gate phase: thread owns (batch gb, unit gu) ----
        {
            float pi = bias0, pf = bias1, pg = bias2, po = bias3;
#pragma unroll
            for (int k8 = 0; k8 < 8; k8++) {
                pi += preX[(0 * 16 + gu) * PRELD + k8 * 17 + gb];
                pf += preX[(1 * 16 + gu) * PRELD + k8 * 17 + gb];
                pg += preX[(2 * 16 + gu) * PRELD + k8 * 17 + gb];
                po += preX[(3 * 16 + gu) * PRELD + k8 * 17 + gb];
            }
            if (t > 0) {
#pragma unroll
                for (int k8 = 0; k8 < 8; k8++) {
                    pi += preH[(0 * 16 + gu) * PRELD + k8 * 17 + gb];
                    pf += preH[(1 * 16 + gu) * PRELD + k8 * 17 + gb];
                    pg += preH[(2 * 16 + gu) * PRELD + k8 * 17 + gb];
                    po += preH[(3 * 16 + gu) * PRELD + k8 * 17 + gb];
                }
            }
            c_state = sigf(pf) * c_state + sigf(pi) * tanhfast(pg);
            const float hv = sigf(po) * tanhfast(c_state);
            __stcg(&g_h[((size_t)(dir * BATCH + b_glob) * SEQ + pos) * HDIM2 + unit], hv);
        }

        __syncthreads();   // all h stores done before release
        if (tid == 0) {
            __threadfence();
            atomicAdd(&g_cnt[cnt_idx], 1);
        }
    }
}

// ============================================================================
// Output projection
// ============================================================================
__global__ __launch_bounds__(256) void feats_kernel(
    const float* __restrict__ wout, const float* __restrict__ bout)
{
    __shared__ float wsm[NTAGS * 512];
    const int tid = threadIdx.x;
    for (int i = tid; i < NTAGS * 512; i += 256) wsm[i] = wout[i];
    __syncthreads();

    const int lane = tid & 31;
    const int warp = tid >> 5;

#pragma unroll
    for (int pass = 0; pass < 4; pass++) {
        const int m = blockIdx.x * 32 + pass * 8 + warp;
        const float* h0 = g_h + (size_t)m * HDIM2;
        const float* h1 = g_h + (size_t)NTOK * HDIM2 + (size_t)m * HDIM2;
        float acc[NTAGS];
#pragma unroll
        for (int tg = 0; tg < NTAGS; tg++) acc[tg] = 0.f;

#pragma unroll
        for (int kk = 0; kk < 16; kk++) {
            const int k = kk * 32 + lane;
            const float hv = (k < 256) ? h0[k] : h1[k - 256];
#pragma unroll
            for (int tg = 0; tg < NTAGS; tg++) acc[tg] += hv * wsm[tg * 512 + k];
        }
#pragma unroll
        for (int tg = 0; tg < NTAGS; tg++)
            for (int off = 16; off; off >>= 1)
                acc[tg] += __shfl_down_sync(0xffffffffu, acc[tg], off);
        if (lane == 0) {
#pragma unroll
            for (int tg = 0; tg < NTAGS; tg++)
                g_feats[(size_t)m * NTAGS + tg] = acc[tg] + bout[tg];
        }
    }
}

// ============================================================================
// CRF per-sequence llh (mask all-ones)
// ============================================================================
__global__ __launch_bounds__(32) void crf_kernel(
    const int* __restrict__ tags,
    const float* __restrict__ startt, const float* __restrict__ endt,
    const float* __restrict__ trans)
{
    const int b = blockIdx.x;
    const int lane = threadIdx.x;
    const float* __restrict__ em = g_feats + (size_t)b * SEQ * NTAGS;
    const int* __restrict__ tg = tags + (size_t)b * SEQ;

    float sc = 0.f;
    for (int s = lane; s < SEQ; s += 32) {
        const int tc = tg[s];
        sc += em[s * NTAGS + tc];
        if (s > 0) sc += trans[tg[s - 1] * NTAGS + tc];
    }
    for (int off = 16; off; off >>= 1) sc += __shfl_down_sync(0xffffffffu, sc, off);

    const int j = lane < NTAGS ? lane : NTAGS - 1;
    float tcol[NTAGS];
#pragma unroll
    for (int i = 0; i < NTAGS; i++) tcol[i] = trans[i * NTAGS + j];

    float alpha = startt[j] + em[j];
    for (int s = 1; s < SEQ; s++) {
        float v[NTAGS];
        float mx = -1e30f;
#pragma unroll
        for (int i = 0; i < NTAGS; i++) {
            const float ai = __shfl_sync(0xffffffffu, alpha, i);
            v[i] = ai + tcol[i];
            mx = fmaxf(mx, v[i]);
        }
        float sum = 0.f;
#pragma unroll
        for (int i = 0; i < NTAGS; i++) sum += __expf(v[i] - mx);
        alpha = mx + __logf(sum) + em[s * NTAGS + j];
    }

    float z = (lane < NTAGS) ? (alpha + endt[j]) : -1e30f;
    float mz = z;
    for (int off = 16; off; off >>= 1) mz = fmaxf(mz, __shfl_down_sync(0xffffffffu, mz, off));
    mz = __shfl_sync(0xffffffffu, mz, 0);
    float ez = __expf(z - mz);
    for (int off = 16; off; off >>= 1) ez += __shfl_down_sync(0xffffffffu, ez, off);

    if (lane == 0) {
        const float logZ = mz + __logf(ez);
        const float score = sc + startt[tg[0]] + endt[tg[SEQ - 1]];
        g_llh[b] = score - logZ;
    }
}

__global__ void final_kernel(float* out) {
    __shared__ float red[64];
    const int t = threadIdx.x;
    red[t] = g_llh[t];
    __syncthreads();
    for (int off = 32; off; off >>= 1) {
        if (t < off) red[t] += red[t + off];
        __syncthreads();
    }
    if (t == 0) out[0] = -red[0] / (float)BATCH;
}

// ============================================================================
#define LSTM_SMEM ((3*16*HLD + 2*64*PRELD) * 4)

extern "C" void kernel_launch(void* const* d_in, const int* in_sizes, int n_in,
                              void* d_out, int out_size)
{
    const int*   sent  = (const int*)  d_in[0];
    const int*   tags  = (const int*)  d_in[1];
    const float* emb   = (const float*)d_in[3];
    const float* wihf  = (const float*)d_in[4];
    const float* whhf  = (const float*)d_in[5];
    const float* bihf  = (const float*)d_in[6];
    const float* bhhf  = (const float*)d_in[7];
    const float* wihb  = (const float*)d_in[8];
    const float* whhb  = (const float*)d_in[9];
    const float* bihb  = (const float*)d_in[10];
    const float* bhhb  = (const float*)d_in[11];
    const float* wout  = (const float*)d_in[12];
    const float* bout  = (const float*)d_in[13];
    const float* startt= (const float*)d_in[14];
    const float* endt  = (const float*)d_in[15];
    const float* trans = (const float*)d_in[16];

    cudaFuncSetAttribute(bilstm_kernel, cudaFuncAttributeMaxDynamicSharedMemorySize, LSTM_SMEM);

    init_kernel<<<1, 32>>>();
    bilstm_kernel<<<128, 256, LSTM_SMEM>>>(wihf, whhf, bihf, bhhf,
                                           wihb, whhb, bihb, bhhb, sent, emb);
    feats_kernel<<<1024, 256>>>(wout, bout);
    crf_kernel<<<64, 32>>>(tags, startt, endt, trans);
    final_kernel<<<1, 64>>>((float*)d_out);
}

// round 9
// speedup vs baseline: 1.6250x; 1.4118x over previous
#include <cuda_runtime.h>
#include <math.h>
#include <cstdint>

#define BATCH 64
#define SEQ   512
#define EDIM  256
#define HDIM2 256
#define G4H   1024
#define NTAGS 9
#define NTOK  (BATCH*SEQ)

typedef unsigned long long u64;

__device__ float g_xg[2u*NTOK*G4H];
__device__ float g_h [2u*NTOK*HDIM2];
__device__ float g_feats[NTOK*NTAGS];
__device__ float g_llh[BATCH];
__device__ int   g_cnt[16];   // per-(dir,bg8) step counters

__device__ __forceinline__ void fma2(u64& acc, u64 a, u64 b) {
    asm("fma.rn.f32x2 %0, %1, %2, %0;" : "+l"(acc) : "l"(a), "l"(b));
}
__device__ __forceinline__ u64 pack2(float x, float y) {
    u64 r; asm("mov.b64 %0, {%1, %2};" : "=l"(r) : "f"(x), "f"(y)); return r;
}
__device__ __forceinline__ float foldlohi(u64 v) {
    float lo, hi; asm("mov.b64 {%0, %1}, %2;" : "=f"(lo), "=f"(hi) : "l"(v)); return lo + hi;
}
__device__ __forceinline__ float2 unpk(u64 v) {
    float2 r; asm("mov.b64 {%0, %1}, %2;" : "=f"(r.x), "=f"(r.y) : "l"(v)); return r;
}
__device__ __forceinline__ float sigf(float x) { return __fdividef(1.f, 1.f + __expf(-x)); }
__device__ __forceinline__ float tanhfast(float x) {
    return 2.f * __fdividef(1.f, 1.f + __expf(-2.f * x)) - 1.f;
}

// ============================================================================
// Kernel 1: fused embedding-gather + input projection SGEMM (f32x2)
//   M=32768, N=2048 (dir-major), K=256. BM=128, BN=128, BK=16, 256 thr, 8x8.
// ============================================================================
__global__ __launch_bounds__(256) void gemm_xg_kernel(
    const int* __restrict__ sent,
    const float* __restrict__ emb,
    const float* __restrict__ wihf, const float* __restrict__ wihb,
    const float* __restrict__ bihf, const float* __restrict__ bhhf,
    const float* __restrict__ bihb, const float* __restrict__ bhhb)
{
    __shared__ float As[16 * 132];
    __shared__ float Bs[16 * 128];

    const int tid = threadIdx.x;
    if (blockIdx.x == 0 && blockIdx.y == 0 && tid < 16) g_cnt[tid] = 0;  // reset lstm counters

    const int ntile = blockIdx.x;
    const int mtile = blockIdx.y;
    const int dir   = ntile >> 3;
    const float* __restrict__ W = dir ? wihb : wihf;

    const int rowA = tid >> 2;
    const int f4k  = tid & 3;
    const int idx0 = sent[mtile * 128 + rowA];
    const int idx1 = sent[mtile * 128 + rowA + 64];
    const int nlb0 = (ntile * 128 + rowA) & 1023;
    const int nlb1 = (ntile * 128 + rowA + 64) & 1023;

    float4 av0 = *reinterpret_cast<const float4*>(emb + (size_t)idx0 * EDIM + f4k * 4);
    float4 av1 = *reinterpret_cast<const float4*>(emb + (size_t)idx1 * EDIM + f4k * 4);
    float4 bv0 = *reinterpret_cast<const float4*>(W + (size_t)nlb0 * EDIM + f4k * 4);
    float4 bv1 = *reinterpret_cast<const float4*>(W + (size_t)nlb1 * EDIM + f4k * 4);

    u64 acc[4][8];
#pragma unroll
    for (int i = 0; i < 4; i++)
#pragma unroll
        for (int j = 0; j < 8; j++) acc[i][j] = 0ull;

    const int ty = tid >> 4, tx = tid & 15;

    for (int kb = 0; kb < EDIM; kb += 16) {
        As[(f4k * 4 + 0) * 132 + rowA] = av0.x;
        As[(f4k * 4 + 1) * 132 + rowA] = av0.y;
        As[(f4k * 4 + 2) * 132 + rowA] = av0.z;
        As[(f4k * 4 + 3) * 132 + rowA] = av0.w;
        As[(f4k * 4 + 0) * 132 + rowA + 64] = av1.x;
        As[(f4k * 4 + 1) * 132 + rowA + 64] = av1.y;
        As[(f4k * 4 + 2) * 132 + rowA + 64] = av1.z;
        As[(f4k * 4 + 3) * 132 + rowA + 64] = av1.w;
        Bs[(f4k * 4 + 0) * 128 + rowA] = bv0.x;
        Bs[(f4k * 4 + 1) * 128 + rowA] = bv0.y;
        Bs[(f4k * 4 + 2) * 128 + rowA] = bv0.z;
        Bs[(f4k * 4 + 3) * 128 + rowA] = bv0.w;
        Bs[(f4k * 4 + 0) * 128 + rowA + 64] = bv1.x;
        Bs[(f4k * 4 + 1) * 128 + rowA + 64] = bv1.y;
        Bs[(f4k * 4 + 2) * 128 + rowA + 64] = bv1.z;
        Bs[(f4k * 4 + 3) * 128 + rowA + 64] = bv1.w;
        __syncthreads();

        if (kb + 16 < EDIM) {
            av0 = *reinterpret_cast<const float4*>(emb + (size_t)idx0 * EDIM + kb + 16 + f4k * 4);
            av1 = *reinterpret_cast<const float4*>(emb + (size_t)idx1 * EDIM + kb + 16 + f4k * 4);
            bv0 = *reinterpret_cast<const float4*>(W + (size_t)nlb0 * EDIM + kb + 16 + f4k * 4);
            bv1 = *reinterpret_cast<const float4*>(W + (size_t)nlb1 * EDIM + kb + 16 + f4k * 4);
        }

#pragma unroll
        for (int k = 0; k < 16; k++) {
            const float* ap = As + k * 132 + ty * 8;
            ulonglong2 A01 = *reinterpret_cast<const ulonglong2*>(ap);
            ulonglong2 A23 = *reinterpret_cast<const ulonglong2*>(ap + 4);
            const float* bp = Bs + k * 128 + tx * 8;
            float4 b0 = *reinterpret_cast<const float4*>(bp);
            float4 b1 = *reinterpret_cast<const float4*>(bp + 4);
            u64 am[4] = {A01.x, A01.y, A23.x, A23.y};
            u64 bn[8];
            bn[0] = pack2(b0.x, b0.x); bn[1] = pack2(b0.y, b0.y);
            bn[2] = pack2(b0.z, b0.z); bn[3] = pack2(b0.w, b0.w);
            bn[4] = pack2(b1.x, b1.x); bn[5] = pack2(b1.y, b1.y);
            bn[6] = pack2(b1.z, b1.z); bn[7] = pack2(b1.w, b1.w);
#pragma unroll
            for (int i = 0; i < 4; i++)
#pragma unroll
                for (int j = 0; j < 8; j++) fma2(acc[i][j], am[i], bn[j]);
        }
        __syncthreads();
    }

    const int n0  = ntile * 128 + tx * 8;
    const int nl0 = n0 & 1023;
    const float* __restrict__ bih = dir ? bihb : bihf;
    const float* __restrict__ bhh = dir ? bhhb : bhhf;
    float bias[8];
#pragma unroll
    for (int j = 0; j < 8; j++) bias[j] = bih[nl0 + j] + bhh[nl0 + j];

#pragma unroll
    for (int i2 = 0; i2 < 4; i2++) {
        float2 v[8];
#pragma unroll
        for (int j = 0; j < 8; j++) v[j] = unpk(acc[i2][j]);
        const int m0 = mtile * 128 + ty * 8 + 2 * i2;
        float4 oa0, oa1, ob0, ob1;
        oa0.x = v[0].x + bias[0]; oa0.y = v[1].x + bias[1]; oa0.z = v[2].x + bias[2]; oa0.w = v[3].x + bias[3];
        oa1.x = v[4].x + bias[4]; oa1.y = v[5].x + bias[5]; oa1.z = v[6].x + bias[6]; oa1.w = v[7].x + bias[7];
        ob0.x = v[0].y + bias[0]; ob0.y = v[1].y + bias[1]; ob0.z = v[2].y + bias[2]; ob0.w = v[3].y + bias[3];
        ob1.x = v[4].y + bias[4]; ob1.y = v[5].y + bias[5]; ob1.z = v[6].y + bias[6]; ob1.w = v[7].y + bias[7];
        float* p0 = g_xg + ((size_t)dir * NTOK + m0) * G4H + nl0;
        float* p1 = g_xg + ((size_t)dir * NTOK + m0 + 1) * G4H + nl0;
        *reinterpret_cast<float4*>(p0)     = oa0;
        *reinterpret_cast<float4*>(p0 + 4) = oa1;
        *reinterpret_cast<float4*>(p1)     = ob0;
        *reinterpret_cast<float4*>(p1 + 4) = ob1;
    }
}

// ============================================================================
// Kernel 2: persistent BiLSTM. 128 CTAs = dir(2) x bg(8) x ug(8).
//   Barrier group = 8 CTAs (vs 16): halved atomic chain, max-of-8 jitter.
//   CTA owns 32 units (128 gate rows) x 8 batches. Weights register-resident:
//   thread (r4 0..31, kc 0..7) holds 4 rows (one per gate) x 32 k = 128 regs.
//   Accumulators in 2 passes of 4 batches (32 u64 live) to bound registers.
//   Handshake = R2-proven counter (fence + RED-add, tid0 spin).
// ============================================================================
#define HLD    260
#define PRE_LD 65

__global__ __launch_bounds__(256, 1) void lstm_kernel(
    const float* __restrict__ whhf, const float* __restrict__ whhb)
{
    __shared__ float hs[8 * HLD];        // staged h_prev [batch][256]
    __shared__ float pre[128 * PRE_LD];  // [row][kc*8 + b]

    const int tid = threadIdx.x;
    const int blk = blockIdx.x;
    const int dir = blk >> 6;
    const int bg  = (blk >> 3) & 7;
    const int ug  = blk & 7;
    const float* __restrict__ whh = dir ? whhb : whhf;

    const int kc = tid & 7;           // k slice
    const int r4 = tid >> 3;          // local unit 0..31 -> rows G*256 + ug*32 + r4

    // register weights: 4 gate rows x 32 k (16 pairs) each
    u64 w[4][16];
#pragma unroll
    for (int G = 0; G < 4; G++) {
        const float* wr = whh + (size_t)(G * 256 + ug * 32 + r4) * HDIM2;
#pragma unroll
        for (int q = 0; q < 8; q++) {
            ulonglong2 v = *reinterpret_cast<const ulonglong2*>(wr + q * 32 + kc * 4);
            w[G][2 * q] = v.x; w[G][2 * q + 1] = v.y;
        }
    }

    const int gb = tid >> 5;          // gate phase: batch 0..7
    const int gu = tid & 31;          // unit-in-slice 0..31
    const int b_glob = bg * 8 + gb;
    const int unit = ug * 32 + gu;
    const int cnt_idx = dir * 8 + bg;
    float c_state = 0.f;

    for (int t = 0; t < SEQ; t++) {
        const int pos = dir ? (SEQ - 1 - t) : t;

        // prefetch x-preacts before the inter-CTA wait
        const float* xp = g_xg + ((size_t)dir * NTOK + (size_t)b_glob * SEQ + pos) * G4H + unit;
        float x0 = __ldcs(xp);
        float x1 = __ldcs(xp + 256);
        float x2 = __ldcs(xp + 512);
        float x3 = __ldcs(xp + 768);

        if (t > 0) {
            if (tid == 0) {
                volatile int* c = &g_cnt[cnt_idx];
                const int target = 8 * t;
                while (*c < target) { }
            }
            __syncthreads();
            const int ppos = dir ? (pos + 1) : (pos - 1);
            // stage h_prev for our 8 batches (512 float4 / 256 threads = 2 each)
#pragma unroll
            for (int q = 0; q < 2; q++) {
                const int id = tid + q * 256;
                const int b = id >> 6, kf4 = id & 63;
                float4 v = __ldcg(reinterpret_cast<const float4*>(
                    g_h + ((size_t)(dir * BATCH + bg * 8 + b) * SEQ + ppos) * HDIM2 + kf4 * 4));
                *reinterpret_cast<float4*>(hs + b * HLD + kf4 * 4) = v;
            }
            __syncthreads();

            // matvec: 4 gate rows x 8 batches x 32 k, in 2 passes of 4 batches
#pragma unroll
            for (int p = 0; p < 2; p++) {
                u64 acc[4][4];
#pragma unroll
                for (int G = 0; G < 4; G++)
#pragma unroll
                    for (int b = 0; b < 4; b++) acc[G][b] = 0ull;
#pragma unroll
                for (int q = 0; q < 8; q++) {
#pragma unroll
                    for (int b = 0; b < 4; b++) {
                        const ulonglong2 hv = *reinterpret_cast<const ulonglong2*>(
                            hs + (p * 4 + b) * HLD + q * 32 + kc * 4);
#pragma unroll
                        for (int G = 0; G < 4; G++) {
                            fma2(acc[G][b], w[G][2 * q],     hv.x);
                            fma2(acc[G][b], w[G][2 * q + 1], hv.y);
                        }
                    }
                }
#pragma unroll
                for (int G = 0; G < 4; G++)
#pragma unroll
                    for (int b = 0; b < 4; b++)
                        pre[(G * 32 + r4) * PRE_LD + kc * 8 + p * 4 + b] = foldlohi(acc[G][b]);
            }
            __syncthreads();
        }

        // gate phase: thread owns (batch gb, unit gu)
        {
            float pi = x0, pf = x1, pg = x2, po = x3;
            if (t > 0) {
#pragma unroll
                for (int k8 = 0; k8 < 8; k8++) {
                    pi += pre[(0 * 32 + gu) * PRE_LD + k8 * 8 + gb];
                    pf += pre[(1 * 32 + gu) * PRE_LD + k8 * 8 + gb];
                    pg += pre[(2 * 32 + gu) * PRE_LD + k8 * 8 + gb];
                    po += pre[(3 * 32 + gu) * PRE_LD + k8 * 8 + gb];
                }
            }
            c_state = sigf(pf) * c_state + sigf(pi) * tanhfast(pg);
            const float hv = sigf(po) * tanhfast(c_state);
            __stcg(&g_h[((size_t)(dir * BATCH + b_glob) * SEQ + pos) * HDIM2 + unit], hv);
        }

        __syncthreads();
        if (tid == 0) {
            __threadfence();
            atomicAdd(&g_cnt[cnt_idx], 1);   // result unused -> RED
        }
    }
}

// ============================================================================
// Kernel 3: output projection
// ============================================================================
__global__ __launch_bounds__(256) void feats_kernel(
    const float* __restrict__ wout, const float* __restrict__ bout)
{
    __shared__ float wsm[NTAGS * 512];
    const int tid = threadIdx.x;
    for (int i = tid; i < NTAGS * 512; i += 256) wsm[i] = wout[i];
    __syncthreads();

    const int lane = tid & 31;
    const int warp = tid >> 5;

#pragma unroll
    for (int pass = 0; pass < 4; pass++) {
        const int m = blockIdx.x * 32 + pass * 8 + warp;
        const float* h0 = g_h + (size_t)m * HDIM2;
        const float* h1 = g_h + (size_t)NTOK * HDIM2 + (size_t)m * HDIM2;
        float acc[NTAGS];
#pragma unroll
        for (int tg = 0; tg < NTAGS; tg++) acc[tg] = 0.f;

#pragma unroll
        for (int kk = 0; kk < 16; kk++) {
            const int k = kk * 32 + lane;
            const float hv = (k < 256) ? h0[k] : h1[k - 256];
#pragma unroll
            for (int tg = 0; tg < NTAGS; tg++) acc[tg] += hv * wsm[tg * 512 + k];
        }
#pragma unroll
        for (int tg = 0; tg < NTAGS; tg++)
            for (int off = 16; off; off >>= 1)
                acc[tg] += __shfl_down_sync(0xffffffffu, acc[tg], off);
        if (lane == 0) {
#pragma unroll
            for (int tg = 0; tg < NTAGS; tg++)
                g_feats[(size_t)m * NTAGS + tg] = acc[tg] + bout[tg];
        }
    }
}

// ============================================================================
// Kernel 4: CRF per-sequence llh (mask all-ones)
// ============================================================================
__global__ __launch_bounds__(32) void crf_kernel(
    const int* __restrict__ tags,
    const float* __restrict__ startt, const float* __restrict__ endt,
    const float* __restrict__ trans)
{
    const int b = blockIdx.x;
    const int lane = threadIdx.x;
    const float* __restrict__ em = g_feats + (size_t)b * SEQ * NTAGS;
    const int* __restrict__ tg = tags + (size_t)b * SEQ;

    float sc = 0.f;
    for (int s = lane; s < SEQ; s += 32) {
        const int tc = tg[s];
        sc += em[s * NTAGS + tc];
        if (s > 0) sc += trans[tg[s - 1] * NTAGS + tc];
    }
    for (int off = 16; off; off >>= 1) sc += __shfl_down_sync(0xffffffffu, sc, off);

    const int j = lane < NTAGS ? lane : NTAGS - 1;
    float tcol[NTAGS];
#pragma unroll
    for (int i = 0; i < NTAGS; i++) tcol[i] = trans[i * NTAGS + j];

    float alpha = startt[j] + em[j];
    for (int s = 1; s < SEQ; s++) {
        float v[NTAGS];
        float mx = -1e30f;
#pragma unroll
        for (int i = 0; i < NTAGS; i++) {
            const float ai = __shfl_sync(0xffffffffu, alpha, i);
            v[i] = ai + tcol[i];
            mx = fmaxf(mx, v[i]);
        }
        float sum = 0.f;
#pragma unroll
        for (int i = 0; i < NTAGS; i++) sum += __expf(v[i] - mx);
        alpha = mx + __logf(sum) + em[s * NTAGS + j];
    }

    float z = (lane < NTAGS) ? (alpha + endt[j]) : -1e30f;
    float mz = z;
    for (int off = 16; off; off >>= 1) mz = fmaxf(mz, __shfl_down_sync(0xffffffffu, mz, off));
    mz = __shfl_sync(0xffffffffu, mz, 0);
    float ez = __expf(z - mz);
    for (int off = 16; off; off >>= 1) ez += __shfl_down_sync(0xffffffffu, ez, off);

    if (lane == 0) {
        const float logZ = mz + __logf(ez);
        const float score = sc + startt[tg[0]] + endt[tg[SEQ - 1]];
        g_llh[b] = score - logZ;
    }
}

__global__ void final_kernel(float* out) {
    __shared__ float red[64];
    const int t = threadIdx.x;
    red[t] = g_llh[t];
    __syncthreads();
    for (int off = 32; off; off >>= 1) {
        if (t < off) red[t] += red[t + off];
        __syncthreads();
    }
    if (t == 0) out[0] = -red[0] / (float)BATCH;
}

// ============================================================================
extern "C" void kernel_launch(void* const* d_in, const int* in_sizes, int n_in,
                              void* d_out, int out_size)
{
    const int*   sent  = (const int*)  d_in[0];
    const int*   tags  = (const int*)  d_in[1];
    const float* emb   = (const float*)d_in[3];
    const float* wihf  = (const float*)d_in[4];
    const float* whhf  = (const float*)d_in[5];
    const float* bihf  = (const float*)d_in[6];
    const float* bhhf  = (const float*)d_in[7];
    const float* wihb  = (const float*)d_in[8];
    const float* whhb  = (const float*)d_in[9];
    const float* bihb  = (const float*)d_in[10];
    const float* bhhb  = (const float*)d_in[11];
    const float* wout  = (const float*)d_in[12];
    const float* bout  = (const float*)d_in[13];
    const float* startt= (const float*)d_in[14];
    const float* endt  = (const float*)d_in[15];
    const float* trans = (const float*)d_in[16];

    gemm_xg_kernel<<<dim3(16, 256), 256>>>(sent, emb, wihf, wihb, bihf, bhhf, bihb, bhhb);
    lstm_kernel<<<128, 256>>>(whhf, whhb);
    feats_kernel<<<1024, 256>>>(wout, bout);
    crf_kernel<<<64, 32>>>(tags, startt, endt, trans);
    final_kernel<<<1, 64>>>((float*)d_out);
}